// round 2
// baseline (speedup 1.0000x reference)
#include <cuda_runtime.h>
#include <math.h>

#define NGENES 1000
#define BATCH  128
#define LAT    128
#define HID    512
#define KTILE  64
#define RSA    130          // padded row stride (floats) for transposed A tile; even => 8B-aligned rows
#define NTH    256

// Scratch (device globals are the sanctioned scratch mechanism; no allocs allowed)
__device__ float g_h1[(size_t)NGENES * BATCH * HID];       // [g][m][n]  (256 MB)
__device__ float g_partial[(size_t)NGENES * 4 * BATCH];    // [g][chunk][m] (2 MB)

static const int SMEM_BYTES = (KTILE * RSA + KTILE * 128) * sizeof(float);  // 66048

// ---------- packed f32x2 helpers (Blackwell FFMA2 path: 2 MACs/inst) ----------
__device__ __forceinline__ void ffma2(unsigned long long& d, unsigned long long a, unsigned long long b) {
    asm("fma.rn.f32x2 %0, %1, %2, %0;" : "+l"(d) : "l"(a), "l"(b));
}
__device__ __forceinline__ unsigned long long dup2(float v) {
    unsigned long long r; asm("mov.b64 %0, {%1, %1};" : "=l"(r) : "f"(v)); return r;
}
__device__ __forceinline__ float2 unpk(unsigned long long v) {
    float2 r; asm("mov.b64 {%0, %1}, %2;" : "=f"(r.x), "=f"(r.y) : "l"(v)); return r;
}

__device__ __forceinline__ float gelu_exact(float v) {
    return 0.5f * v * (1.0f + erff(v * 0.70710678118654752440f));
}

// ---------- unified 128(M) x 128(N) x Ktot tile GEMM ----------
// A: [128][lda] row-major (natural); B: [Ktot][ldb] row-major, already offset to column n0.
// Result: cc[i][j] for rows m = ty*8+i, cols n = n0 + tx*8+j.
__device__ __forceinline__ void run_gemm(
    const float* __restrict__ A, int lda,
    const float* __restrict__ Bm, int ldb,
    int Ktot, float* smem, float cc[8][8])
{
    float* aT = smem;                       // [KTILE][RSA]   (A transposed: [k][m])
    float* bs = smem + KTILE * RSA;         // [KTILE][128]

    const int tid = threadIdx.x;
    const int tx = tid & 15;
    const int ty = tid >> 4;

    unsigned long long acc[4][8];
#pragma unroll
    for (int i2 = 0; i2 < 4; ++i2)
#pragma unroll
        for (int j = 0; j < 8; ++j) acc[i2][j] = 0ULL;

    const int ntiles = Ktot / KTILE;
    for (int kt = 0; kt < ntiles; ++kt) {
        // load + transpose A tile: [128 m][KTILE k] -> aT[k][m]
        const float* Ak = A + kt * KTILE;
#pragma unroll 2
        for (int e = tid; e < 128 * KTILE; e += NTH) {
            int m = e >> 6;            // /KTILE
            int kk = e & (KTILE - 1);
            aT[kk * RSA + m] = Ak[(size_t)m * lda + kk];
        }
        // load B tile: [KTILE k][128 n]
        const float* Bk = Bm + (size_t)kt * KTILE * ldb;
#pragma unroll 2
        for (int e = tid; e < KTILE * 128; e += NTH) {
            int kk = e >> 7;
            int n = e & 127;
            bs[kk * 128 + n] = Bk[(size_t)kk * ldb + n];
        }
        __syncthreads();

#pragma unroll 4
        for (int kk = 0; kk < KTILE; ++kk) {
            const unsigned long long* ar =
                reinterpret_cast<const unsigned long long*>(&aT[kk * RSA + ty * 8]);
            unsigned long long a0 = ar[0], a1 = ar[1], a2 = ar[2], a3 = ar[3];
            const float4* br = reinterpret_cast<const float4*>(&bs[kk * 128 + tx * 8]);
            float4 bA = br[0], bB = br[1];
            unsigned long long bb[8];
            bb[0] = dup2(bA.x); bb[1] = dup2(bA.y); bb[2] = dup2(bA.z); bb[3] = dup2(bA.w);
            bb[4] = dup2(bB.x); bb[5] = dup2(bB.y); bb[6] = dup2(bB.z); bb[7] = dup2(bB.w);
#pragma unroll
            for (int j = 0; j < 8; ++j) {
                ffma2(acc[0][j], a0, bb[j]);
                ffma2(acc[1][j], a1, bb[j]);
                ffma2(acc[2][j], a2, bb[j]);
                ffma2(acc[3][j], a3, bb[j]);
            }
        }
        __syncthreads();
    }

#pragma unroll
    for (int i2 = 0; i2 < 4; ++i2)
#pragma unroll
        for (int j = 0; j < 8; ++j) {
            float2 v = unpk(acc[i2][j]);
            cc[2 * i2 + 0][j] = v.x;
            cc[2 * i2 + 1][j] = v.y;
        }
}

// ---------- Kernel 1: h1 = gelu(x @ W1[g] + b1[g]) ----------
__global__ void __launch_bounds__(NTH, 2)
k1_gemm1(const float* __restrict__ x, const float* __restrict__ W1,
         const float* __restrict__ b1)
{
    const int g = blockIdx.x;
    const int nc = blockIdx.y;            // N chunk of 128
    extern __shared__ float smem[];

    float cc[8][8];
    run_gemm(x, LAT,
             W1 + (size_t)g * LAT * HID + nc * 128, HID,
             LAT, smem, cc);

    const int tx = threadIdx.x & 15;
    const int ty = threadIdx.x >> 4;
    const int n0 = nc * 128 + tx * 8;

    float bias[8];
    const float* b1g = b1 + (size_t)g * HID + n0;
#pragma unroll
    for (int j = 0; j < 8; ++j) bias[j] = b1g[j];

    float* hp = g_h1 + (size_t)g * BATCH * HID + n0;
#pragma unroll
    for (int i = 0; i < 8; ++i) {
        int m = ty * 8 + i;
        float4 s0, s1;
        s0.x = gelu_exact(cc[i][0] + bias[0]);
        s0.y = gelu_exact(cc[i][1] + bias[1]);
        s0.z = gelu_exact(cc[i][2] + bias[2]);
        s0.w = gelu_exact(cc[i][3] + bias[3]);
        s1.x = gelu_exact(cc[i][4] + bias[4]);
        s1.y = gelu_exact(cc[i][5] + bias[5]);
        s1.z = gelu_exact(cc[i][6] + bias[6]);
        s1.w = gelu_exact(cc[i][7] + bias[7]);
        *reinterpret_cast<float4*>(&hp[(size_t)m * HID]) = s0;
        *reinterpret_cast<float4*>(&hp[(size_t)m * HID + 4]) = s1;
    }
}

// ---------- Kernel 2: partial[g][nc][m] = sum_n gelu(h1 @ W2 + b2)[m,n] * W3[g][n] ----------
__global__ void __launch_bounds__(NTH, 2)
k2_gemm2(const float* __restrict__ W2, const float* __restrict__ b2,
         const float* __restrict__ W3)
{
    const int g = blockIdx.x;
    const int nc = blockIdx.y;
    extern __shared__ float smem[];

    float cc[8][8];
    run_gemm(g_h1 + (size_t)g * BATCH * HID, HID,
             W2 + (size_t)g * HID * HID + nc * 128, HID,
             HID, smem, cc);

    const int tid = threadIdx.x;
    const int tx = tid & 15;
    const int ty = tid >> 4;
    const int n0 = nc * 128 + tx * 8;

    float bias[8], w3v[8];
    const float* b2g = b2 + (size_t)g * HID + n0;
    const float* w3g = W3 + (size_t)g * HID + n0;
#pragma unroll
    for (int j = 0; j < 8; ++j) { bias[j] = b2g[j]; w3v[j] = w3g[j]; }

    float rs[8];
#pragma unroll
    for (int i = 0; i < 8; ++i) {
        float s = 0.0f;
#pragma unroll
        for (int j = 0; j < 8; ++j)
            s += gelu_exact(cc[i][j] + bias[j]) * w3v[j];
        rs[i] = s;
    }

    // deterministic reduction over tx (16 lanes) via smem (reuse tile buffers)
    float* red = smem;  // [128][17]
    // (last __syncthreads of run_gemm already passed; smem free)
#pragma unroll
    for (int i = 0; i < 8; ++i)
        red[(ty * 8 + i) * 17 + tx] = rs[i];
    __syncthreads();

    if (tid < BATCH) {
        float s = 0.0f;
#pragma unroll
        for (int t = 0; t < 16; ++t) s += red[tid * 17 + t];
        g_partial[((size_t)g * 4 + nc) * BATCH + tid] = s;
    }
}

// ---------- Kernel 3: out[m][g] = b3[g] + sum_c partial[g][c][m] ----------
__global__ void k3_reduce(const float* __restrict__ b3, float* __restrict__ out)
{
    int idx = blockIdx.x * blockDim.x + threadIdx.x;   // over BATCH*NGENES
    if (idx >= BATCH * NGENES) return;
    int m = idx / NGENES;
    int g = idx - m * NGENES;
    float s = b3[g];
#pragma unroll
    for (int c = 0; c < 4; ++c)
        s += g_partial[((size_t)g * 4 + c) * BATCH + m];
    out[(size_t)m * NGENES + g] = s;
}

extern "C" void kernel_launch(void* const* d_in, const int* in_sizes, int n_in,
                              void* d_out, int out_size)
{
    const float* x  = (const float*)d_in[0];
    const float* W1 = (const float*)d_in[1];
    const float* b1 = (const float*)d_in[2];
    const float* W2 = (const float*)d_in[3];
    const float* b2 = (const float*)d_in[4];
    const float* W3 = (const float*)d_in[5];
    const float* b3 = (const float*)d_in[6];
    float* out = (float*)d_out;

    cudaFuncSetAttribute(k1_gemm1, cudaFuncAttributeMaxDynamicSharedMemorySize, SMEM_BYTES);
    cudaFuncSetAttribute(k2_gemm2, cudaFuncAttributeMaxDynamicSharedMemorySize, SMEM_BYTES);

    dim3 grid(NGENES, 4);
    k1_gemm1<<<grid, NTH, SMEM_BYTES>>>(x, W1, b1);
    k2_gemm2<<<grid, NTH, SMEM_BYTES>>>(W2, b2, W3);

    int total = BATCH * NGENES;
    k3_reduce<<<(total + NTH - 1) / NTH, NTH>>>(b3, out);
}

// round 3
// speedup vs baseline: 1.0004x; 1.0004x over previous
#include <cuda_runtime.h>
#include <math.h>

#define NGENES 1000
#define BATCH  128
#define LAT    128
#define HID    512
#define KTILE  64
#define RSA    130          // padded row stride (floats) for transposed A tile; even => 8B-aligned rows
#define NTH    256

// Scratch (device globals are the sanctioned scratch mechanism; no allocs allowed)
__device__ float g_h1[(size_t)NGENES * BATCH * HID];       // [g][m][n]  (256 MB)
__device__ float g_partial[(size_t)NGENES * 4 * BATCH];    // [g][chunk][m] (2 MB)

static const int SMEM_BYTES = (KTILE * RSA + KTILE * 128) * sizeof(float);  // 66048

// ---------- packed f32x2 helpers (Blackwell FFMA2 path: 2 MACs/inst) ----------
__device__ __forceinline__ void ffma2(unsigned long long& d, unsigned long long a, unsigned long long b) {
    asm("fma.rn.f32x2 %0, %1, %2, %0;" : "+l"(d) : "l"(a), "l"(b));
}
__device__ __forceinline__ unsigned long long dup2(float v) {
    unsigned long long r; asm("mov.b64 %0, {%1, %1};" : "=l"(r) : "f"(v)); return r;
}
__device__ __forceinline__ float2 unpk(unsigned long long v) {
    float2 r; asm("mov.b64 {%0, %1}, %2;" : "=f"(r.x), "=f"(r.y) : "l"(v)); return r;
}

__device__ __forceinline__ float gelu_exact(float v) {
    return 0.5f * v * (1.0f + erff(v * 0.70710678118654752440f));
}

// ---------- unified 128(M) x 128(N) x Ktot tile GEMM ----------
// A: [128][lda] row-major (natural); B: [Ktot][ldb] row-major, already offset to column n0.
// Result: cc[i][j] for rows m = ty*8+i, cols n = n0 + tx*8+j.
__device__ __forceinline__ void run_gemm(
    const float* __restrict__ A, int lda,
    const float* __restrict__ Bm, int ldb,
    int Ktot, float* smem, float cc[8][8])
{
    float* aT = smem;                       // [KTILE][RSA]   (A transposed: [k][m])
    float* bs = smem + KTILE * RSA;         // [KTILE][128]

    const int tid = threadIdx.x;
    const int tx = tid & 15;
    const int ty = tid >> 4;

    unsigned long long acc[4][8];
#pragma unroll
    for (int i2 = 0; i2 < 4; ++i2)
#pragma unroll
        for (int j = 0; j < 8; ++j) acc[i2][j] = 0ULL;

    const int ntiles = Ktot / KTILE;
    for (int kt = 0; kt < ntiles; ++kt) {
        // load + transpose A tile: [128 m][KTILE k] -> aT[k][m]
        const float* Ak = A + kt * KTILE;
#pragma unroll 2
        for (int e = tid; e < 128 * KTILE; e += NTH) {
            int m = e >> 6;            // /KTILE
            int kk = e & (KTILE - 1);
            aT[kk * RSA + m] = Ak[(size_t)m * lda + kk];
        }
        // load B tile: [KTILE k][128 n]
        const float* Bk = Bm + (size_t)kt * KTILE * ldb;
#pragma unroll 2
        for (int e = tid; e < KTILE * 128; e += NTH) {
            int kk = e >> 7;
            int n = e & 127;
            bs[kk * 128 + n] = Bk[(size_t)kk * ldb + n];
        }
        __syncthreads();

#pragma unroll 4
        for (int kk = 0; kk < KTILE; ++kk) {
            const unsigned long long* ar =
                reinterpret_cast<const unsigned long long*>(&aT[kk * RSA + ty * 8]);
            unsigned long long a0 = ar[0], a1 = ar[1], a2 = ar[2], a3 = ar[3];
            const float4* br = reinterpret_cast<const float4*>(&bs[kk * 128 + tx * 8]);
            float4 bA = br[0], bB = br[1];
            unsigned long long bb[8];
            bb[0] = dup2(bA.x); bb[1] = dup2(bA.y); bb[2] = dup2(bA.z); bb[3] = dup2(bA.w);
            bb[4] = dup2(bB.x); bb[5] = dup2(bB.y); bb[6] = dup2(bB.z); bb[7] = dup2(bB.w);
#pragma unroll
            for (int j = 0; j < 8; ++j) {
                ffma2(acc[0][j], a0, bb[j]);
                ffma2(acc[1][j], a1, bb[j]);
                ffma2(acc[2][j], a2, bb[j]);
                ffma2(acc[3][j], a3, bb[j]);
            }
        }
        __syncthreads();
    }

#pragma unroll
    for (int i2 = 0; i2 < 4; ++i2)
#pragma unroll
        for (int j = 0; j < 8; ++j) {
            float2 v = unpk(acc[i2][j]);
            cc[2 * i2 + 0][j] = v.x;
            cc[2 * i2 + 1][j] = v.y;
        }
}

// ---------- Kernel 1: h1 = gelu(x @ W1[g] + b1[g]) ----------
__global__ void __launch_bounds__(NTH, 2)
k1_gemm1(const float* __restrict__ x, const float* __restrict__ W1,
         const float* __restrict__ b1)
{
    const int g = blockIdx.x;
    const int nc = blockIdx.y;            // N chunk of 128
    extern __shared__ float smem[];

    float cc[8][8];
    run_gemm(x, LAT,
             W1 + (size_t)g * LAT * HID + nc * 128, HID,
             LAT, smem, cc);

    const int tx = threadIdx.x & 15;
    const int ty = threadIdx.x >> 4;
    const int n0 = nc * 128 + tx * 8;

    float bias[8];
    const float* b1g = b1 + (size_t)g * HID + n0;
#pragma unroll
    for (int j = 0; j < 8; ++j) bias[j] = b1g[j];

    float* hp = g_h1 + (size_t)g * BATCH * HID + n0;
#pragma unroll
    for (int i = 0; i < 8; ++i) {
        int m = ty * 8 + i;
        float4 s0, s1;
        s0.x = gelu_exact(cc[i][0] + bias[0]);
        s0.y = gelu_exact(cc[i][1] + bias[1]);
        s0.z = gelu_exact(cc[i][2] + bias[2]);
        s0.w = gelu_exact(cc[i][3] + bias[3]);
        s1.x = gelu_exact(cc[i][4] + bias[4]);
        s1.y = gelu_exact(cc[i][5] + bias[5]);
        s1.z = gelu_exact(cc[i][6] + bias[6]);
        s1.w = gelu_exact(cc[i][7] + bias[7]);
        *reinterpret_cast<float4*>(&hp[(size_t)m * HID]) = s0;
        *reinterpret_cast<float4*>(&hp[(size_t)m * HID + 4]) = s1;
    }
}

// ---------- Kernel 2: partial[g][nc][m] = sum_n gelu(h1 @ W2 + b2)[m,n] * W3[g][n] ----------
__global__ void __launch_bounds__(NTH, 2)
k2_gemm2(const float* __restrict__ W2, const float* __restrict__ b2,
         const float* __restrict__ W3)
{
    const int g = blockIdx.x;
    const int nc = blockIdx.y;
    extern __shared__ float smem[];

    float cc[8][8];
    run_gemm(g_h1 + (size_t)g * BATCH * HID, HID,
             W2 + (size_t)g * HID * HID + nc * 128, HID,
             HID, smem, cc);

    const int tid = threadIdx.x;
    const int tx = tid & 15;
    const int ty = tid >> 4;
    const int n0 = nc * 128 + tx * 8;

    float bias[8], w3v[8];
    const float* b2g = b2 + (size_t)g * HID + n0;
    const float* w3g = W3 + (size_t)g * HID + n0;
#pragma unroll
    for (int j = 0; j < 8; ++j) { bias[j] = b2g[j]; w3v[j] = w3g[j]; }

    float rs[8];
#pragma unroll
    for (int i = 0; i < 8; ++i) {
        float s = 0.0f;
#pragma unroll
        for (int j = 0; j < 8; ++j)
            s += gelu_exact(cc[i][j] + bias[j]) * w3v[j];
        rs[i] = s;
    }

    // deterministic reduction over tx (16 lanes) via smem (reuse tile buffers)
    float* red = smem;  // [128][17]
    // (last __syncthreads of run_gemm already passed; smem free)
#pragma unroll
    for (int i = 0; i < 8; ++i)
        red[(ty * 8 + i) * 17 + tx] = rs[i];
    __syncthreads();

    if (tid < BATCH) {
        float s = 0.0f;
#pragma unroll
        for (int t = 0; t < 16; ++t) s += red[tid * 17 + t];
        g_partial[((size_t)g * 4 + nc) * BATCH + tid] = s;
    }
}

// ---------- Kernel 3: out[m][g] = b3[g] + sum_c partial[g][c][m] ----------
__global__ void k3_reduce(const float* __restrict__ b3, float* __restrict__ out)
{
    int idx = blockIdx.x * blockDim.x + threadIdx.x;   // over BATCH*NGENES
    if (idx >= BATCH * NGENES) return;
    int m = idx / NGENES;
    int g = idx - m * NGENES;
    float s = b3[g];
#pragma unroll
    for (int c = 0; c < 4; ++c)
        s += g_partial[((size_t)g * 4 + c) * BATCH + m];
    out[(size_t)m * NGENES + g] = s;
}

extern "C" void kernel_launch(void* const* d_in, const int* in_sizes, int n_in,
                              void* d_out, int out_size)
{
    const float* x  = (const float*)d_in[0];
    const float* W1 = (const float*)d_in[1];
    const float* b1 = (const float*)d_in[2];
    const float* W2 = (const float*)d_in[3];
    const float* b2 = (const float*)d_in[4];
    const float* W3 = (const float*)d_in[5];
    const float* b3 = (const float*)d_in[6];
    float* out = (float*)d_out;

    cudaFuncSetAttribute(k1_gemm1, cudaFuncAttributeMaxDynamicSharedMemorySize, SMEM_BYTES);
    cudaFuncSetAttribute(k2_gemm2, cudaFuncAttributeMaxDynamicSharedMemorySize, SMEM_BYTES);

    dim3 grid(NGENES, 4);
    k1_gemm1<<<grid, NTH, SMEM_BYTES>>>(x, W1, b1);
    k2_gemm2<<<grid, NTH, SMEM_BYTES>>>(W2, b2, W3);

    int total = BATCH * NGENES;
    k3_reduce<<<(total + NTH - 1) / NTH, NTH>>>(b3, out);
}

// round 5
// speedup vs baseline: 3.2029x; 3.2017x over previous
#include <cuda_runtime.h>
#include <math.h>
#include <stdint.h>

#define NG 1000

// scratch: h1 as separate bf16-hi / bf16-lo planes, packed 2 halves per u32
__device__ __align__(16) uint32_t g_h1h[(size_t)NG * 128 * 256];
__device__ __align__(16) uint32_t g_h1l[(size_t)NG * 128 * 256];
__device__ float g_part[(size_t)NG * 4 * 128];

#define SM1_BYTES 132096   // 1024 hdr + 4*32KB planes
#define SM2_BYTES 135168   // 4096 hdr + 2 stages * 64KB

__device__ __forceinline__ uint32_t smem_u32(const void* p){
    uint32_t a;
    asm("{ .reg .u64 t; cvta.to.shared.u64 t, %1; cvt.u32.u64 %0, t; }" : "=r"(a) : "l"(p));
    return a;
}
__device__ __forceinline__ uint32_t sw(uint32_t x){ return x ^ ((x >> 3) & 0x70u); }

__device__ __forceinline__ void split2(float f0, float f1, uint32_t& hp, uint32_t& lp){
    asm("cvt.rn.bf16x2.f32 %0, %1, %2;" : "=r"(hp) : "f"(f1), "f"(f0));
    float h1f = __uint_as_float(hp & 0xFFFF0000u);
    float h0f = __uint_as_float(hp << 16);
    asm("cvt.rn.bf16x2.f32 %0, %1, %2;" : "=r"(lp) : "f"(f1 - h1f), "f"(f0 - h0f));
}
__device__ __forceinline__ float gelu(float v){
    return 0.5f * v * (1.0f + erff(v * 0.70710678118654752440f));
}
__device__ __forceinline__ void ldsm4(uint32_t* r, uint32_t a){
    asm volatile("ldmatrix.sync.aligned.m8n8.x4.shared.b16 {%0,%1,%2,%3}, [%4];"
      : "=r"(r[0]), "=r"(r[1]), "=r"(r[2]), "=r"(r[3]) : "r"(a));
}
__device__ __forceinline__ void mmabf(float* c, const uint32_t* a, uint32_t b0, uint32_t b1){
    asm volatile("mma.sync.aligned.m16n8k16.row.col.f32.bf16.bf16.f32 "
      "{%0,%1,%2,%3},{%4,%5,%6,%7},{%8,%9},{%0,%1,%2,%3};"
      : "+f"(c[0]), "+f"(c[1]), "+f"(c[2]), "+f"(c[3])
      : "r"(a[0]), "r"(a[1]), "r"(a[2]), "r"(a[3]), "r"(b0), "r"(b1));
}
#define CP16(d,s)  asm volatile("cp.async.cg.shared.global [%0], [%1], 16;" :: "r"(d), "l"(s) : "memory")
#define CPCOMMIT() asm volatile("cp.async.commit_group;" ::: "memory")
#define CPWAIT0()  asm volatile("cp.async.wait_group 0;" ::: "memory")

struct Frag { uint32_t offA, mA, offB, mB, ksel; };

__device__ __forceinline__ Frag mk_frag(int lane, int wm, int wn){
    Frag f;
    uint32_t rA = wm * 64 + (lane & 7) + ((lane >> 3) & 1) * 8;
    uint32_t rB = wn * 32 + (lane & 7) + ((lane >> 3) & 1) * 8;
    f.ksel = ((lane >> 4) & 1) * 16;
    f.mA = (rA & 7) << 4;  f.mB = (rB & 7) << 4;
    f.offA = rA * 128;     f.offB = rB * 128;
    return f;
}

// one K=64 tile: A/B hi+lo planes, [row][64k] bf16, 128B rows, SW128 swizzled
__device__ __forceinline__ void mma_ktile(uint32_t Ah, uint32_t Al, uint32_t Bh, uint32_t Bl,
                                          const Frag& f, float c[4][4][4])
{
#pragma unroll
    for (int ks = 0; ks < 4; ks++){
        uint32_t ka = ks * 32 + f.ksel;
        uint32_t ao = f.offA + (ka ^ f.mA);
        uint32_t bo = f.offB + (ka ^ f.mB);
        uint32_t ah[4][4], al[4][4], bh[2][4], bl[2][4];
#pragma unroll
        for (int i = 0; i < 4; i++){ ldsm4(ah[i], Ah + ao + i*2048u); ldsm4(al[i], Al + ao + i*2048u); }
#pragma unroll
        for (int j = 0; j < 2; j++){ ldsm4(bh[j], Bh + bo + j*2048u); ldsm4(bl[j], Bl + bo + j*2048u); }
#pragma unroll
        for (int i = 0; i < 4; i++)
#pragma unroll
        for (int jt = 0; jt < 4; jt++){
            int j = jt >> 1, s2 = jt & 1;
            mmabf(c[i][jt], ah[i], bh[j][s2], bh[j][s2+2]);
            mmabf(c[i][jt], ah[i], bl[j][s2], bl[j][s2+2]);
            mmabf(c[i][jt], al[i], bh[j][s2], bh[j][s2+2]);
        }
    }
}

// ============ k1: h1 = gelu(x @ W1 + b1) -> bf16 hi/lo planes ============
// grid (1000, 4): gene, 128-col chunk. smem: b1s@0, planes@1024:
// Ah(kt)@1024+kt*16K, Al@+32K, Bh@+64K, Bl@+96K
__global__ void __launch_bounds__(256, 1)
k1(const float* __restrict__ x, const float* __restrict__ W1, const float* __restrict__ b1)
{
    extern __shared__ char sm[];
    uint32_t sb = smem_u32(sm);
    const int g = blockIdx.x, nc = blockIdx.y;
    const int tid = threadIdx.x, lane = tid & 31, w = tid >> 5;
    const int wm = w & 1, wn = w >> 1;

    float* b1s = (float*)sm;
    if (tid < 128) b1s[tid] = b1[(size_t)g * 512 + nc * 128 + tid];

    // A = x split into bf16 hi/lo, 2 K-tiles of 64
    {
        int m = tid >> 1, h = tid & 1;
        const float4* xr = (const float4*)(x + m * 128 + h * 64);
        char* Ah = sm + 1024 + h * 16384;
        char* Al = sm + 1024 + 32768 + h * 16384;
#pragma unroll
        for (int j = 0; j < 16; j++){
            float4 v = xr[j];
            uint32_t hp0, lp0, hp1, lp1;
            split2(v.x, v.y, hp0, lp0);
            split2(v.z, v.w, hp1, lp1);
            uint32_t off = sw(m * 128 + j * 8);
            *(uint2*)(Ah + off) = make_uint2(hp0, hp1);
            *(uint2*)(Al + off) = make_uint2(lp0, lp1);
        }
    }
    // B = W1 chunk, [n][k] layout
    {
        int n = tid & 127, kh = tid >> 7;
        const float* wp = W1 + (size_t)g * 65536 + (size_t)kh * 64 * 512 + nc * 128 + n;
        char* Bh = sm + 1024 + 65536 + kh * 16384;
        char* Bl = sm + 1024 + 98304 + kh * 16384;
#pragma unroll 4
        for (int l = 0; l < 64; l += 4){
            float f0 = wp[(l+0)*512], f1 = wp[(l+1)*512];
            float f2 = wp[(l+2)*512], f3 = wp[(l+3)*512];
            uint32_t hp0, lp0, hp1, lp1;
            split2(f0, f1, hp0, lp0);
            split2(f2, f3, hp1, lp1);
            uint32_t off = sw(n * 128 + l * 2);
            *(uint2*)(Bh + off) = make_uint2(hp0, hp1);
            *(uint2*)(Bl + off) = make_uint2(lp0, lp1);
        }
    }
    __syncthreads();

    float c[4][4][4];
#pragma unroll
    for (int i = 0; i < 4; i++)
#pragma unroll
    for (int jt = 0; jt < 4; jt++)
#pragma unroll
    for (int q = 0; q < 4; q++) c[i][jt][q] = 0.0f;

    Frag f = mk_frag(lane, wm, wn);
#pragma unroll
    for (int kt = 0; kt < 2; kt++)
        mma_ktile(sb + 1024 + kt*16384, sb + 1024 + 32768 + kt*16384,
                  sb + 1024 + 65536 + kt*16384, sb + 1024 + 98304 + kt*16384, f, c);

    // epilogue: bias + gelu + split-pack -> g_h1h / g_h1l
#pragma unroll
    for (int i = 0; i < 4; i++)
#pragma unroll
    for (int jt = 0; jt < 4; jt++){
        int nl = wn * 32 + jt * 8 + 2 * (lane & 3);
        int r0 = wm * 64 + i * 16 + (lane >> 2);
        float bb0 = b1s[nl], bb1 = b1s[nl + 1];
        uint32_t hp, lp;
        float v0 = gelu(c[i][jt][0] + bb0);
        float v1 = gelu(c[i][jt][1] + bb1);
        split2(v0, v1, hp, lp);
        size_t idx = (size_t)g * 32768 + (size_t)r0 * 256 + (nc * 128 + nl) / 2;
        g_h1h[idx] = hp; g_h1l[idx] = lp;
        v0 = gelu(c[i][jt][2] + bb0);
        v1 = gelu(c[i][jt][3] + bb1);
        split2(v0, v1, hp, lp);
        idx += (size_t)8 * 256;
        g_h1h[idx] = hp; g_h1l[idx] = lp;
    }
}

// ============ k2: partial = sum_n gelu(h1 @ W2 + b2) * W3 ============
// grid (1000, 4). smem: b2s@0, w3s@512, red@1024(2KB), stages@4096 (Ah,Al,Bh,Bl 16KB each)
__global__ void __launch_bounds__(256, 1)
k2(const float* __restrict__ W2, const float* __restrict__ b2, const float* __restrict__ W3)
{
    extern __shared__ char sm[];
    uint32_t sb = smem_u32(sm);
    const int g = blockIdx.x, nc = blockIdx.y;
    const int tid = threadIdx.x, lane = tid & 31, w = tid >> 5;
    const int wm = w & 1, wn = w >> 1;

    float* b2s = (float*)sm;
    float* w3s = (float*)(sm + 512);
    if (tid < 128){
        b2s[tid] = b2[(size_t)g * 512 + nc * 128 + tid];
        w3s[tid] = W3[(size_t)g * 512 + nc * 128 + tid];
    }

    const char* hsrc = (const char*)g_h1h + (size_t)g * 131072;
    const char* lsrc = (const char*)g_h1l + (size_t)g * 131072;
    const int n = tid & 127, kh = tid >> 7;
    const float* pB = W2 + (size_t)g * 262144 + (size_t)kh * 32 * 512 + nc * 128 + n;
    const uint32_t bOff = sw((uint32_t)n * 128 + (uint32_t)kh * 64);  // kh*32 halves = 64B

    float c[4][4][4];
#pragma unroll
    for (int i = 0; i < 4; i++)
#pragma unroll
    for (int jt = 0; jt < 4; jt++)
#pragma unroll
    for (int q = 0; q < 4; q++) c[i][jt][q] = 0.0f;

    Frag f = mk_frag(lane, wm, wn);

    // ---- prologue: tile 0 ----
    {
        uint32_t AhB = sb + 4096, AlB = AhB + 16384;
#pragma unroll
        for (int i2 = 0; i2 < 4; i2++){
            uint32_t gi = tid + i2 * 256, m = gi >> 3, kb = gi & 7;
            uint32_t d = sw(m * 128 + kb * 16);
            size_t so = (size_t)m * 1024 + kb * 16;
            CP16(AhB + d, hsrc + so);
            CP16(AlB + d, lsrc + so);
        }
        CPCOMMIT();
        float fB[32];
#pragma unroll
        for (int l = 0; l < 32; l++) fB[l] = pB[(size_t)l * 512];
        char* Bh = sm + 4096 + 32768; char* Bl = sm + 4096 + 49152;
#pragma unroll
        for (int l = 0; l < 32; l += 4){
            uint32_t hp0, lp0, hp1, lp1;
            split2(fB[l], fB[l+1], hp0, lp0);
            split2(fB[l+2], fB[l+3], hp1, lp1);
            uint32_t off = sw(n * 128 + (kh * 32 + l) * 2);
            *(uint2*)(Bh + off) = make_uint2(hp0, hp1);
            *(uint2*)(Bl + off) = make_uint2(lp0, lp1);
        }
        CPWAIT0();
    }
    __syncthreads();

    for (int kt = 0; kt < 8; kt++){
        const int buf = kt & 1;
        const uint32_t cur = sb + 4096 + buf * 65536;
        const uint32_t nxt = sb + 4096 + (buf ^ 1) * 65536;
        float fN[32];
        if (kt < 7){
#pragma unroll
            for (int i2 = 0; i2 < 4; i2++){
                uint32_t gi = tid + i2 * 256, m = gi >> 3, kb = gi & 7;
                uint32_t d = sw(m * 128 + kb * 16);
                size_t so = (size_t)m * 1024 + (size_t)(kt + 1) * 128 + kb * 16;
                CP16(nxt + d, hsrc + so);
                CP16(nxt + 16384 + d, lsrc + so);
            }
            CPCOMMIT();
#pragma unroll
            for (int l = 0; l < 32; l++)
                fN[l] = pB[(size_t)((kt + 1) * 64 + l) * 512];
        }

        mma_ktile(cur, cur + 16384, cur + 32768, cur + 49152, f, c);

        if (kt < 7){
            CPWAIT0();
            char* Bh = sm + 4096 + (buf ^ 1) * 65536 + 32768;
            char* Bl = Bh + 16384;
#pragma unroll
            for (int l = 0; l < 32; l += 4){
                uint32_t hp0, lp0, hp1, lp1;
                split2(fN[l], fN[l+1], hp0, lp0);
                split2(fN[l+2], fN[l+3], hp1, lp1);
                uint32_t off = sw(n * 128 + (kh * 32 + l) * 2);
                *(uint2*)(Bh + off) = make_uint2(hp0, hp1);
                *(uint2*)(Bl + off) = make_uint2(lp0, lp1);
            }
        }
        __syncthreads();
    }

    // epilogue: bias + gelu + W3-dot, quad shuffle + cross-warp smem reduce
    float* red = (float*)(sm + 1024);
#pragma unroll
    for (int i = 0; i < 4; i++){
        float s0 = 0.0f, s1 = 0.0f;
#pragma unroll
        for (int jt = 0; jt < 4; jt++){
            int nl = wn * 32 + jt * 8 + 2 * (lane & 3);
            float bb0 = b2s[nl], bb1 = b2s[nl+1], ww0 = w3s[nl], ww1 = w3s[nl+1];
            s0 += gelu(c[i][jt][0] + bb0) * ww0 + gelu(c[i][jt][1] + bb1) * ww1;
            s1 += gelu(c[i][jt][2] + bb0) * ww0 + gelu(c[i][jt][3] + bb1) * ww1;
        }
        s0 += __shfl_xor_sync(0xFFFFFFFFu, s0, 1);
        s0 += __shfl_xor_sync(0xFFFFFFFFu, s0, 2);
        s1 += __shfl_xor_sync(0xFFFFFFFFu, s1, 1);
        s1 += __shfl_xor_sync(0xFFFFFFFFu, s1, 2);
        if ((lane & 3) == 0){
            int r0 = wm * 64 + i * 16 + (lane >> 2);
            red[r0 * 4 + wn] = s0;
            red[(r0 + 8) * 4 + wn] = s1;
        }
    }
    __syncthreads();
    if (tid < 128){
        float v = red[tid*4] + red[tid*4+1] + red[tid*4+2] + red[tid*4+3];
        g_part[((size_t)g * 4 + nc) * 128 + tid] = v;
    }
}

// ============ k3 ============
__global__ void k3(const float* __restrict__ b3, float* __restrict__ out)
{
    int idx = blockIdx.x * 256 + threadIdx.x;
    if (idx >= 128 * NG) return;
    int m = idx / NG;
    int g = idx - m * NG;
    const float* p = g_part + (size_t)g * 512 + m;
    out[idx] = b3[g] + ((p[0] + p[128]) + (p[256] + p[384]));
}

extern "C" void kernel_launch(void* const* d_in, const int* in_sizes, int n_in,
                              void* d_out, int out_size)
{
    const float* x  = (const float*)d_in[0];
    const float* W1 = (const float*)d_in[1];
    const float* b1 = (const float*)d_in[2];
    const float* W2 = (const float*)d_in[3];
    const float* b2 = (const float*)d_in[4];
    const float* W3 = (const float*)d_in[5];
    const float* b3 = (const float*)d_in[6];
    float* out = (float*)d_out;

    cudaFuncSetAttribute(k1, cudaFuncAttributeMaxDynamicSharedMemorySize, SM1_BYTES);
    cudaFuncSetAttribute(k2, cudaFuncAttributeMaxDynamicSharedMemorySize, SM2_BYTES);

    dim3 grid(NG, 4);
    k1<<<grid, 256, SM1_BYTES>>>(x, W1, b1);
    k2<<<grid, 256, SM2_BYTES>>>(W2, b2, W3);
    k3<<<(128 * NG + 255) / 256, 256>>>(b3, out);
}